// round 12
// baseline (speedup 1.0000x reference)
#include <cuda_runtime.h>
#include <cstdint>

#define TS 65536

// Scratch (device globals — allocation-free per harness rules)
__device__ float g_xg[(size_t)TS * 1024];   // permuted gate preactivations
__device__ float g_hs[(size_t)TS * 256];    // per-step hidden outputs

__device__ __forceinline__ uint32_t smem_u32(const void* p) {
    uint32_t r;
    asm("{ .reg .u64 t; cvta.to.shared.u64 t, %1; cvt.u32.u64 %0, t; }" : "=r"(r) : "l"(p));
    return r;
}

__device__ __forceinline__ float tanhapx(float x) {
    float y;
    asm("tanh.approx.f32 %0, %1;" : "=f"(y) : "f"(x));
    return y;
}
// sigmoid via tanh: sig(x) = 0.5 + 0.5*tanh(0.5x)
__device__ __forceinline__ float sigapx(float x) {
    return 0.5f + 0.5f * tanhapx(0.5f * x);
}
// accurate sigmoid for the fc epilogue (not on critical path)
__device__ __forceinline__ float fsig(float x) {
    return __fdividef(1.0f, 1.0f + __expf(-x));
}

// ---------------------------------------------------------------------------
// GEMM 1: xg[t][r] = b1[r]+b2[r] + sum_k x[t][k] * W_ih2[r][k]
// stored permuted: g_xg[t*1024 + u*4 + g], r = g*256+u  (gate order i,f,g,o)
// ---------------------------------------------------------------------------
__global__ __launch_bounds__(256) void gemm_xg_kernel(
    const float* __restrict__ X,    // [65536,256]
    const float* __restrict__ W,    // [1024,256]
    const float* __restrict__ b1,
    const float* __restrict__ b2)
{
    __shared__ float Xs[32][65];
    __shared__ float Ws[32][65];
    const int lin = threadIdx.x;
    const int tx = lin & 15, ty = lin >> 4;
    const int bt = blockIdx.x * 64;
    const int br = blockIdx.y * 64;
    float acc[4][4] = {};

    for (int k0 = 0; k0 < 256; k0 += 32) {
        int row = lin >> 3, seg = (lin & 7) << 2;
        float4 v = *(const float4*)&X[(size_t)(bt + row) * 256 + k0 + seg];
        Xs[seg+0][row] = v.x; Xs[seg+1][row] = v.y; Xs[seg+2][row] = v.z; Xs[seg+3][row] = v.w;
        float4 v2 = *(const float4*)&X[(size_t)(bt + row + 32) * 256 + k0 + seg];
        Xs[seg+0][row+32] = v2.x; Xs[seg+1][row+32] = v2.y; Xs[seg+2][row+32] = v2.z; Xs[seg+3][row+32] = v2.w;
        float4 w1 = *(const float4*)&W[(size_t)(br + row) * 256 + k0 + seg];
        Ws[seg+0][row] = w1.x; Ws[seg+1][row] = w1.y; Ws[seg+2][row] = w1.z; Ws[seg+3][row] = w1.w;
        float4 w2 = *(const float4*)&W[(size_t)(br + row + 32) * 256 + k0 + seg];
        Ws[seg+0][row+32] = w2.x; Ws[seg+1][row+32] = w2.y; Ws[seg+2][row+32] = w2.z; Ws[seg+3][row+32] = w2.w;
        __syncthreads();
#pragma unroll
        for (int kk = 0; kk < 32; kk++) {
            float a[4], bb[4];
#pragma unroll
            for (int i = 0; i < 4; i++) a[i] = Xs[kk][ty*4 + i];
#pragma unroll
            for (int j = 0; j < 4; j++) bb[j] = Ws[kk][tx*4 + j];
#pragma unroll
            for (int i = 0; i < 4; i++)
#pragma unroll
                for (int j = 0; j < 4; j++) acc[i][j] = fmaf(a[i], bb[j], acc[i][j]);
        }
        __syncthreads();
    }
#pragma unroll
    for (int j = 0; j < 4; j++) {
        int r = br + tx*4 + j;
        float bias = b1[r] + b2[r];
        int u = r & 255, g = r >> 8;
#pragma unroll
        for (int i = 0; i < 4; i++) {
            int t = bt + ty*4 + i;
            g_xg[(size_t)t * 1024 + u*4 + g] = acc[i][j] + bias;
        }
    }
}

// ---------------------------------------------------------------------------
// Sequential scan: one 8-CTA cluster. W_hh2 register-resident (128 regs/thr).
// tid = ul*8 + part ; unit u = rank*32+ul ; cols [part*32, part*32+32).
// hv loads use ROTATED chunk order q=(j+part)&7 so that at each micro-step
// the 8 parts of a warp hit 8 distinct bank groups (conflict-free), instead
// of all hitting banks {4q..4q+3} (8-way conflict).
// Exchange: R10 scheme — leaders (part==0) scalar st.async to all 8 CTAs;
// wait via mbarrier try_wait acquire.cta on all warps.
// ---------------------------------------------------------------------------
__global__ void __cluster_dims__(8, 1, 1) __launch_bounds__(256, 1)
scan_kernel(const float* __restrict__ Whh,
            const float* __restrict__ h0,
            const float* __restrict__ c0)
{
    __shared__ __align__(16) float hb[2][256];
    __shared__ __align__(8)  unsigned long long mbars[2];

    const int tid  = threadIdx.x;
    const int part = tid & 7;
    const int ul   = tid >> 3;
    uint32_t rank;
    asm("mov.u32 %0, %%cluster_ctarank;" : "=r"(rank));
    const int u    = (int)rank * 32 + ul;
    const int col0 = part * 32;

    // W rows {g*256+u}, cols [col0,col0+32) as f32x2 pairs -> 64 ull regs
    unsigned long long w[4][16];
#pragma unroll
    for (int g = 0; g < 4; g++) {
        const unsigned long long* wp =
            (const unsigned long long*)(Whh + (size_t)(g * 256 + u) * 256 + col0);
#pragma unroll
        for (int j = 0; j < 16; j++) w[g][j] = wp[j];
    }

    const uint32_t hb0 = smem_u32(&hb[0][0]);
    const uint32_t mb0 = smem_u32(&mbars[0]);
    const uint32_t mb_delta = mb0 - hb0;

    if (tid == 0) {
        asm volatile("mbarrier.init.shared.b64 [%0], 1;" :: "r"(mb0) : "memory");
        asm volatile("mbarrier.init.shared.b64 [%0], 1;" :: "r"(mb0 + 8) : "memory");
        // pre-arm both buffers (h_1 -> mbar[1], h_2 -> mbar[0]); 256 * 4B
        asm volatile("mbarrier.arrive.expect_tx.shared.b64 _, [%0], %1;" :: "r"(mb0), "r"(1024u) : "memory");
        asm volatile("mbarrier.arrive.expect_tx.shared.b64 _, [%0], %1;" :: "r"(mb0 + 8), "r"(1024u) : "memory");
    }
    hb[0][tid] = h0[tid];          // every CTA preloads full h0 (256 threads)
    __syncthreads();
    asm volatile("barrier.cluster.arrive.aligned;" ::: "memory");
    asm volatile("barrier.cluster.wait.aligned;"   ::: "memory");

    // replicated recurrent state (all 8 lanes of a unit group carry c)
    float c = c0[u];

    // remote hb base addresses (used by leaders only)
    uint32_t r_hb[8];
#pragma unroll
    for (int k = 0; k < 8; k++)
        asm("mapa.shared::cluster.u32 %0, %1, %2;" : "=r"(r_hb[k]) : "r"(hb0), "r"(k));

    // xg for this thread's unit (all lanes load; 8-lane groups share sectors)
    float4 xg_c = *(const float4*)(g_xg + (size_t)0 * 1024 + u * 4);
    float4 xg_n = *(const float4*)(g_xg + (size_t)1 * 1024 + u * 4);

    uint32_t par0 = 0u, par1 = 0u;

    for (int t = 0; t < TS; t++) {
        const int buf = t & 1;
        if (t > 0) {
            const uint32_t mb = mb0 + (uint32_t)buf * 8u;
            const uint32_t p  = buf ? par1 : par0;
            uint32_t done;
            do {
                asm volatile(
                    "{\n\t.reg .pred P;\n\t"
                    "mbarrier.try_wait.parity.acquire.cta.shared::cta.b64 P, [%1], %2, 0x989680;\n\t"
                    "selp.b32 %0, 1, 0, P;\n\t}"
                    : "=r"(done) : "r"(mb), "r"(p) : "memory");
            } while (!done);
            if (buf) par1 ^= 1u; else par0 ^= 1u;
            // re-arm for h_{t+2}; safe: producers of h_{t+2} need tid0's h_{t+1},
            // which tid0 sends only after this re-arm.
            if (tid == 0 && t + 2 < TS)
                asm volatile("mbarrier.arrive.expect_tx.shared.b64 _, [%0], %1;" :: "r"(mb), "r"(1024u) : "memory");
        }

        // prefetch xg for t+2 (all lanes; group-shared sectors)
        float4 xg2 = make_float4(0.f,0.f,0.f,0.f);
        if (t + 2 < TS)
            xg2 = *(const float4*)(g_xg + (size_t)(t + 2) * 1024 + u * 4);

        // load 32 h values as 16 f32x2, chunk order rotated by part so the
        // 8 parts of a warp hit distinct banks at each micro-step
        unsigned long long hv[16];
        {
            const ulonglong2* h2 = (const ulonglong2*)&hb[buf][col0];
#pragma unroll
            for (int jj = 0; jj < 8; jj++) {
                const int q = (jj + part) & 7;
                ulonglong2 v = h2[q];
                hv[2*q]     = v.x;
                hv[2*q + 1] = v.y;
            }
        }

        unsigned long long a0 = 0ull, a1 = 0ull, a2 = 0ull, a3 = 0ull;
#pragma unroll
        for (int j = 0; j < 16; j++) {
            asm("fma.rn.f32x2 %0, %1, %2, %0;" : "+l"(a0) : "l"(w[0][j]), "l"(hv[j]));
            asm("fma.rn.f32x2 %0, %1, %2, %0;" : "+l"(a1) : "l"(w[1][j]), "l"(hv[j]));
            asm("fma.rn.f32x2 %0, %1, %2, %0;" : "+l"(a2) : "l"(w[2][j]), "l"(hv[j]));
            asm("fma.rn.f32x2 %0, %1, %2, %0;" : "+l"(a3) : "l"(w[3][j]), "l"(hv[j]));
        }

        float s0, s1, s2, s3;
        {
            uint32_t lo, hi;
            asm("mov.b64 {%0,%1}, %2;" : "=r"(lo), "=r"(hi) : "l"(a0));
            s0 = __uint_as_float(lo) + __uint_as_float(hi);
            asm("mov.b64 {%0,%1}, %2;" : "=r"(lo), "=r"(hi) : "l"(a1));
            s1 = __uint_as_float(lo) + __uint_as_float(hi);
            asm("mov.b64 {%0,%1}, %2;" : "=r"(lo), "=r"(hi) : "l"(a2));
            s2 = __uint_as_float(lo) + __uint_as_float(hi);
            asm("mov.b64 {%0,%1}, %2;" : "=r"(lo), "=r"(hi) : "l"(a3));
            s3 = __uint_as_float(lo) + __uint_as_float(hi);
        }
#pragma unroll
        for (int m = 4; m; m >>= 1) {
            s0 += __shfl_xor_sync(0xffffffffu, s0, m);
            s1 += __shfl_xor_sync(0xffffffffu, s1, m);
            s2 += __shfl_xor_sync(0xffffffffu, s2, m);
            s3 += __shfl_xor_sync(0xffffffffu, s3, m);
        }

        // all lanes compute the unit update (replicated; no divergent region)
        float ii = sigapx (xg_c.x + s0);
        float ff = sigapx (xg_c.y + s1);
        float gg = tanhapx(xg_c.z + s2);
        float oo = sigapx (xg_c.w + s3);
        c = ff * c + ii * gg;
        float hnew = oo * tanhapx(c);

        if (part == 0) {
            g_hs[(size_t)t * 256 + u] = hnew;
            if (t + 1 < TS) {
                const uint32_t hval = __float_as_uint(hnew);
                const int nbuf = buf ^ 1;
                const uint32_t doff = (uint32_t)(nbuf * 256 + u) * 4u;
                const uint32_t moff = mb_delta + (uint32_t)nbuf * 8u;
#pragma unroll
                for (int k = 0; k < 8; k++) {
                    asm volatile(
                        "st.async.weak.shared::cluster.mbarrier::complete_tx::bytes.b32 [%0], %1, [%2];"
                        :: "r"(r_hb[k] + doff), "r"(hval), "r"(r_hb[k] + moff) : "memory");
                }
            }
        }

        xg_c = xg_n;
        xg_n = xg2;
    }
}

// ---------------------------------------------------------------------------
// GEMM 2 + epilogue: out[t][r] = 2*sigmoid( sum_k hs[t][k]*fc_W[r][k] + fc_b[r] )
// ---------------------------------------------------------------------------
__global__ __launch_bounds__(256) void fc_kernel(
    const float* __restrict__ Wf,   // [256,256]
    const float* __restrict__ bf,
    float* __restrict__ out)
{
    __shared__ float Xs[32][65];
    __shared__ float Ws[32][65];
    const int lin = threadIdx.x;
    const int tx = lin & 15, ty = lin >> 4;
    const int bt = blockIdx.x * 64;
    const int br = blockIdx.y * 64;
    float acc[4][4] = {};

    for (int k0 = 0; k0 < 256; k0 += 32) {
        int row = lin >> 3, seg = (lin & 7) << 2;
        float4 v = *(const float4*)&g_hs[(size_t)(bt + row) * 256 + k0 + seg];
        Xs[seg+0][row] = v.x; Xs[seg+1][row] = v.y; Xs[seg+2][row] = v.z; Xs[seg+3][row] = v.w;
        float4 v2 = *(const float4*)&g_hs[(size_t)(bt + row + 32) * 256 + k0 + seg];
        Xs[seg+0][row+32] = v2.x; Xs[seg+1][row+32] = v2.y; Xs[seg+2][row+32] = v2.z; Xs[seg+3][row+32] = v2.w;
        float4 w1 = *(const float4*)&Wf[(size_t)(br + row) * 256 + k0 + seg];
        Ws[seg+0][row] = w1.x; Ws[seg+1][row] = w1.y; Ws[seg+2][row] = w1.z; Ws[seg+3][row] = w1.w;
        float4 w2 = *(const float4*)&Wf[(size_t)(br + row + 32) * 256 + k0 + seg];
        Ws[seg+0][row+32] = w2.x; Ws[seg+1][row+32] = w2.y; Ws[seg+2][row+32] = w2.z; Ws[seg+3][row+32] = w2.w;
        __syncthreads();
#pragma unroll
        for (int kk = 0; kk < 32; kk++) {
            float a[4], bb[4];
#pragma unroll
            for (int i = 0; i < 4; i++) a[i] = Xs[kk][ty*4 + i];
#pragma unroll
            for (int j = 0; j < 4; j++) bb[j] = Ws[kk][tx*4 + j];
#pragma unroll
            for (int i = 0; i < 4; i++)
#pragma unroll
                for (int j = 0; j < 4; j++) acc[i][j] = fmaf(a[i], bb[j], acc[i][j]);
        }
        __syncthreads();
    }
#pragma unroll
    for (int j = 0; j < 4; j++) {
        int r = br + tx*4 + j;
        float bias = bf[r];
#pragma unroll
        for (int i = 0; i < 4; i++) {
            int t = bt + ty*4 + i;
            out[(size_t)t * 256 + r] = 2.0f * fsig(acc[i][j] + bias);
        }
    }
}

// ---------------------------------------------------------------------------
extern "C" void kernel_launch(void* const* d_in, const int* in_sizes, int n_in,
                              void* d_out, int out_size)
{
    (void)in_sizes; (void)n_in; (void)out_size;
    const float* x      = (const float*)d_in[0];
    const float* W_ih2  = (const float*)d_in[7];
    const float* W_hh2  = (const float*)d_in[8];
    const float* b_ih2  = (const float*)d_in[9];
    const float* b_hh2  = (const float*)d_in[10];
    const float* h0_2   = (const float*)d_in[11];
    const float* c0_2   = (const float*)d_in[12];
    const float* fc_W   = (const float*)d_in[13];
    const float* fc_b   = (const float*)d_in[14];
    float* out = (float*)d_out;

    gemm_xg_kernel<<<dim3(TS / 64, 16), 256>>>(x, W_ih2, b_ih2, b_hh2);
    scan_kernel<<<8, 256>>>(W_hh2, h0_2, c0_2);
    fc_kernel<<<dim3(TS / 64, 4), 256>>>(fc_W, fc_b, out);
}

// round 13
// speedup vs baseline: 5.1138x; 5.1138x over previous
#include <cuda_runtime.h>
#include <cstdint>

#define TS 65536

// Scratch (device globals — allocation-free per harness rules)
__device__ float g_xg[(size_t)TS * 1024];   // permuted gate preactivations
__device__ float g_hs[(size_t)TS * 256];    // per-step hidden outputs

__device__ __forceinline__ uint32_t smem_u32(const void* p) {
    uint32_t r;
    asm("{ .reg .u64 t; cvta.to.shared.u64 t, %1; cvt.u32.u64 %0, t; }" : "=r"(r) : "l"(p));
    return r;
}

__device__ __forceinline__ float tanhapx(float x) {
    float y;
    asm("tanh.approx.f32 %0, %1;" : "=f"(y) : "f"(x));
    return y;
}
// sigmoid via tanh: sig(x) = 0.5 + 0.5*tanh(0.5x)
__device__ __forceinline__ float sigapx(float x) {
    return 0.5f + 0.5f * tanhapx(0.5f * x);
}
// accurate sigmoid for the fc epilogue (not on critical path)
__device__ __forceinline__ float fsig(float x) {
    return __fdividef(1.0f, 1.0f + __expf(-x));
}

// ---------------------------------------------------------------------------
// GEMM 1: xg[t][r] = b1[r]+b2[r] + sum_k x[t][k] * W_ih2[r][k]
// stored permuted: g_xg[t*1024 + u*4 + g], r = g*256+u  (gate order i,f,g,o)
// ---------------------------------------------------------------------------
__global__ __launch_bounds__(256) void gemm_xg_kernel(
    const float* __restrict__ X,    // [65536,256]
    const float* __restrict__ W,    // [1024,256]
    const float* __restrict__ b1,
    const float* __restrict__ b2)
{
    __shared__ float Xs[32][65];
    __shared__ float Ws[32][65];
    const int lin = threadIdx.x;
    const int tx = lin & 15, ty = lin >> 4;
    const int bt = blockIdx.x * 64;
    const int br = blockIdx.y * 64;
    float acc[4][4] = {};

    for (int k0 = 0; k0 < 256; k0 += 32) {
        int row = lin >> 3, seg = (lin & 7) << 2;
        float4 v = *(const float4*)&X[(size_t)(bt + row) * 256 + k0 + seg];
        Xs[seg+0][row] = v.x; Xs[seg+1][row] = v.y; Xs[seg+2][row] = v.z; Xs[seg+3][row] = v.w;
        float4 v2 = *(const float4*)&X[(size_t)(bt + row + 32) * 256 + k0 + seg];
        Xs[seg+0][row+32] = v2.x; Xs[seg+1][row+32] = v2.y; Xs[seg+2][row+32] = v2.z; Xs[seg+3][row+32] = v2.w;
        float4 w1 = *(const float4*)&W[(size_t)(br + row) * 256 + k0 + seg];
        Ws[seg+0][row] = w1.x; Ws[seg+1][row] = w1.y; Ws[seg+2][row] = w1.z; Ws[seg+3][row] = w1.w;
        float4 w2 = *(const float4*)&W[(size_t)(br + row + 32) * 256 + k0 + seg];
        Ws[seg+0][row+32] = w2.x; Ws[seg+1][row+32] = w2.y; Ws[seg+2][row+32] = w2.z; Ws[seg+3][row+32] = w2.w;
        __syncthreads();
#pragma unroll
        for (int kk = 0; kk < 32; kk++) {
            float a[4], bb[4];
#pragma unroll
            for (int i = 0; i < 4; i++) a[i] = Xs[kk][ty*4 + i];
#pragma unroll
            for (int j = 0; j < 4; j++) bb[j] = Ws[kk][tx*4 + j];
#pragma unroll
            for (int i = 0; i < 4; i++)
#pragma unroll
                for (int j = 0; j < 4; j++) acc[i][j] = fmaf(a[i], bb[j], acc[i][j]);
        }
        __syncthreads();
    }
#pragma unroll
    for (int j = 0; j < 4; j++) {
        int r = br + tx*4 + j;
        float bias = b1[r] + b2[r];
        int u = r & 255, g = r >> 8;
#pragma unroll
        for (int i = 0; i < 4; i++) {
            int t = bt + ty*4 + i;
            g_xg[(size_t)t * 1024 + u*4 + g] = acc[i][j] + bias;
        }
    }
}

// ---------------------------------------------------------------------------
// Sequential scan: one 8-CTA cluster. W_hh2 register-resident (128 regs/thr).
// tid = ul*8 + part ; unit u = rank*32+ul ; cols [part*32, part*32+32).
// Bank-conflict-free hv loads: at micro-step jj, part p reads the 16B chunk
// (jj+p)&7 of its window (addresses rotated at runtime, DESTINATION indices
// hv[2*jj] compile-time -> stays in registers). Weights are loaded in the
// SAME rotated chunk order so hv[j] pairs with w[g][j].
// Exchange: R10 scheme — leaders (part==0) scalar st.async to all 8 CTAs;
// wait via mbarrier try_wait acquire.cta on all warps.
// ---------------------------------------------------------------------------
__global__ void __cluster_dims__(8, 1, 1) __launch_bounds__(256, 1)
scan_kernel(const float* __restrict__ Whh,
            const float* __restrict__ h0,
            const float* __restrict__ c0)
{
    __shared__ __align__(16) float hb[2][256];
    __shared__ __align__(8)  unsigned long long mbars[2];

    const int tid  = threadIdx.x;
    const int part = tid & 7;
    const int ul   = tid >> 3;
    uint32_t rank;
    asm("mov.u32 %0, %%cluster_ctarank;" : "=r"(rank));
    const int u    = (int)rank * 32 + ul;
    const int col0 = part * 32;

    // W rows {g*256+u}, cols in ROTATED chunk order: pair slot 2*jj holds
    // logical chunk q=(jj+part)&7 (4 floats = 2 f32x2), matching hv below.
    unsigned long long w[4][16];
#pragma unroll
    for (int g = 0; g < 4; g++) {
        const float* wrow = Whh + (size_t)(g * 256 + u) * 256 + col0;
#pragma unroll
        for (int jj = 0; jj < 8; jj++) {
            const int q = (jj + part) & 7;
            const unsigned long long* wp = (const unsigned long long*)(wrow + 4 * q);
            w[g][2*jj]     = wp[0];
            w[g][2*jj + 1] = wp[1];
        }
    }

    const uint32_t hb0 = smem_u32(&hb[0][0]);
    const uint32_t mb0 = smem_u32(&mbars[0]);
    const uint32_t mb_delta = mb0 - hb0;

    if (tid == 0) {
        asm volatile("mbarrier.init.shared.b64 [%0], 1;" :: "r"(mb0) : "memory");
        asm volatile("mbarrier.init.shared.b64 [%0], 1;" :: "r"(mb0 + 8) : "memory");
        // pre-arm both buffers (h_1 -> mbar[1], h_2 -> mbar[0]); 256 * 4B
        asm volatile("mbarrier.arrive.expect_tx.shared.b64 _, [%0], %1;" :: "r"(mb0), "r"(1024u) : "memory");
        asm volatile("mbarrier.arrive.expect_tx.shared.b64 _, [%0], %1;" :: "r"(mb0 + 8), "r"(1024u) : "memory");
    }
    hb[0][tid] = h0[tid];          // every CTA preloads full h0 (256 threads)
    __syncthreads();
    asm volatile("barrier.cluster.arrive.aligned;" ::: "memory");
    asm volatile("barrier.cluster.wait.aligned;"   ::: "memory");

    // leader-only state
    float c = 0.0f;
    uint32_t r_hb[8];
    float4 xg_c = make_float4(0.f,0.f,0.f,0.f), xg_n = xg_c;
    if (part == 0) {
        c = c0[u];
#pragma unroll
        for (int k = 0; k < 8; k++)
            asm("mapa.shared::cluster.u32 %0, %1, %2;" : "=r"(r_hb[k]) : "r"(hb0), "r"(k));
        xg_c = *(const float4*)(g_xg + (size_t)0 * 1024 + u * 4);
        xg_n = *(const float4*)(g_xg + (size_t)1 * 1024 + u * 4);
    }

    uint32_t par0 = 0u, par1 = 0u;

    for (int t = 0; t < TS; t++) {
        const int buf = t & 1;
        if (t > 0) {
            const uint32_t mb = mb0 + (uint32_t)buf * 8u;
            const uint32_t p  = buf ? par1 : par0;
            uint32_t done;
            do {
                asm volatile(
                    "{\n\t.reg .pred P;\n\t"
                    "mbarrier.try_wait.parity.acquire.cta.shared::cta.b64 P, [%1], %2, 0x989680;\n\t"
                    "selp.b32 %0, 1, 0, P;\n\t}"
                    : "=r"(done) : "r"(mb), "r"(p) : "memory");
            } while (!done);
            if (buf) par1 ^= 1u; else par0 ^= 1u;
            // re-arm for h_{t+2}; safe: producers of h_{t+2} need tid0's h_{t+1},
            // which tid0 sends only after this re-arm.
            if (tid == 0 && t + 2 < TS)
                asm volatile("mbarrier.arrive.expect_tx.shared.b64 _, [%0], %1;" :: "r"(mb), "r"(1024u) : "memory");
        }

        // prefetch xg for t+2 (leaders only)
        float4 xg2 = make_float4(0.f,0.f,0.f,0.f);
        if (part == 0 && t + 2 < TS)
            xg2 = *(const float4*)(g_xg + (size_t)(t + 2) * 1024 + u * 4);

        // load 32 h values as 16 f32x2, chunk addresses rotated by part so the
        // 8 parts of a warp hit disjoint bank groups at each micro-step.
        // hv indices are COMPILE-TIME (2*jj) -> registers, no spill.
        unsigned long long hv[16];
        {
            const float* hwin = &hb[buf][col0];
#pragma unroll
            for (int jj = 0; jj < 8; jj++) {
                const int q = (jj + part) & 7;
                ulonglong2 v = *(const ulonglong2*)(hwin + 4 * q);
                hv[2*jj]     = v.x;
                hv[2*jj + 1] = v.y;
            }
        }

        unsigned long long a0 = 0ull, a1 = 0ull, a2 = 0ull, a3 = 0ull;
#pragma unroll
        for (int j = 0; j < 16; j++) {
            asm("fma.rn.f32x2 %0, %1, %2, %0;" : "+l"(a0) : "l"(w[0][j]), "l"(hv[j]));
            asm("fma.rn.f32x2 %0, %1, %2, %0;" : "+l"(a1) : "l"(w[1][j]), "l"(hv[j]));
            asm("fma.rn.f32x2 %0, %1, %2, %0;" : "+l"(a2) : "l"(w[2][j]), "l"(hv[j]));
            asm("fma.rn.f32x2 %0, %1, %2, %0;" : "+l"(a3) : "l"(w[3][j]), "l"(hv[j]));
        }

        float s0, s1, s2, s3;
        {
            uint32_t lo, hi;
            asm("mov.b64 {%0,%1}, %2;" : "=r"(lo), "=r"(hi) : "l"(a0));
            s0 = __uint_as_float(lo) + __uint_as_float(hi);
            asm("mov.b64 {%0,%1}, %2;" : "=r"(lo), "=r"(hi) : "l"(a1));
            s1 = __uint_as_float(lo) + __uint_as_float(hi);
            asm("mov.b64 {%0,%1}, %2;" : "=r"(lo), "=r"(hi) : "l"(a2));
            s2 = __uint_as_float(lo) + __uint_as_float(hi);
            asm("mov.b64 {%0,%1}, %2;" : "=r"(lo), "=r"(hi) : "l"(a3));
            s3 = __uint_as_float(lo) + __uint_as_float(hi);
        }
#pragma unroll
        for (int m = 4; m; m >>= 1) {
            s0 += __shfl_xor_sync(0xffffffffu, s0, m);
            s1 += __shfl_xor_sync(0xffffffffu, s1, m);
            s2 += __shfl_xor_sync(0xffffffffu, s2, m);
            s3 += __shfl_xor_sync(0xffffffffu, s3, m);
        }

        if (part == 0) {
            float ii = sigapx (xg_c.x + s0);
            float ff = sigapx (xg_c.y + s1);
            float gg = tanhapx(xg_c.z + s2);
            float oo = sigapx (xg_c.w + s3);
            c = ff * c + ii * gg;
            float hnew = oo * tanhapx(c);
            g_hs[(size_t)t * 256 + u] = hnew;
            if (t + 1 < TS) {
                const uint32_t hval = __float_as_uint(hnew);
                const int nbuf = buf ^ 1;
                const uint32_t doff = (uint32_t)(nbuf * 256 + u) * 4u;
                const uint32_t moff = mb_delta + (uint32_t)nbuf * 8u;
#pragma unroll
                for (int k = 0; k < 8; k++) {
                    asm volatile(
                        "st.async.weak.shared::cluster.mbarrier::complete_tx::bytes.b32 [%0], %1, [%2];"
                        :: "r"(r_hb[k] + doff), "r"(hval), "r"(r_hb[k] + moff) : "memory");
                }
            }
            xg_c = xg_n;
            xg_n = xg2;
        }
    }
}

// ---------------------------------------------------------------------------
// GEMM 2 + epilogue: out[t][r] = 2*sigmoid( sum_k hs[t][k]*fc_W[r][k] + fc_b[r] )
// ---------------------------------------------------------------------------
__global__ __launch_bounds__(256) void fc_kernel(
    const float* __restrict__ Wf,   // [256,256]
    const float* __restrict__ bf,
    float* __restrict__ out)
{
    __shared__ float Xs[32][65];
    __shared__ float Ws[32][65];
    const int lin = threadIdx.x;
    const int tx = lin & 15, ty = lin >> 4;
    const int bt = blockIdx.x * 64;
    const int br = blockIdx.y * 64;
    float acc[4][4] = {};

    for (int k0 = 0; k0 < 256; k0 += 32) {
        int row = lin >> 3, seg = (lin & 7) << 2;
        float4 v = *(const float4*)&g_hs[(size_t)(bt + row) * 256 + k0 + seg];
        Xs[seg+0][row] = v.x; Xs[seg+1][row] = v.y; Xs[seg+2][row] = v.z; Xs[seg+3][row] = v.w;
        float4 v2 = *(const float4*)&g_hs[(size_t)(bt + row + 32) * 256 + k0 + seg];
        Xs[seg+0][row+32] = v2.x; Xs[seg+1][row+32] = v2.y; Xs[seg+2][row+32] = v2.z; Xs[seg+3][row+32] = v2.w;
        float4 w1 = *(const float4*)&Wf[(size_t)(br + row) * 256 + k0 + seg];
        Ws[seg+0][row] = w1.x; Ws[seg+1][row] = w1.y; Ws[seg+2][row] = w1.z; Ws[seg+3][row] = w1.w;
        float4 w2 = *(const float4*)&Wf[(size_t)(br + row + 32) * 256 + k0 + seg];
        Ws[seg+0][row+32] = w2.x; Ws[seg+1][row+32] = w2.y; Ws[seg+2][row+32] = w2.z; Ws[seg+3][row+32] = w2.w;
        __syncthreads();
#pragma unroll
        for (int kk = 0; kk < 32; kk++) {
            float a[4], bb[4];
#pragma unroll
            for (int i = 0; i < 4; i++) a[i] = Xs[kk][ty*4 + i];
#pragma unroll
            for (int j = 0; j < 4; j++) bb[j] = Ws[kk][tx*4 + j];
#pragma unroll
            for (int i = 0; i < 4; i++)
#pragma unroll
                for (int j = 0; j < 4; j++) acc[i][j] = fmaf(a[i], bb[j], acc[i][j]);
        }
        __syncthreads();
    }
#pragma unroll
    for (int j = 0; j < 4; j++) {
        int r = br + tx*4 + j;
        float bias = bf[r];
#pragma unroll
        for (int i = 0; i < 4; i++) {
            int t = bt + ty*4 + i;
            out[(size_t)t * 256 + r] = 2.0f * fsig(acc[i][j] + bias);
        }
    }
}

// ---------------------------------------------------------------------------
extern "C" void kernel_launch(void* const* d_in, const int* in_sizes, int n_in,
                              void* d_out, int out_size)
{
    (void)in_sizes; (void)n_in; (void)out_size;
    const float* x      = (const float*)d_in[0];
    const float* W_ih2  = (const float*)d_in[7];
    const float* W_hh2  = (const float*)d_in[8];
    const float* b_ih2  = (const float*)d_in[9];
    const float* b_hh2  = (const float*)d_in[10];
    const float* h0_2   = (const float*)d_in[11];
    const float* c0_2   = (const float*)d_in[12];
    const float* fc_W   = (const float*)d_in[13];
    const float* fc_b   = (const float*)d_in[14];
    float* out = (float*)d_out;

    gemm_xg_kernel<<<dim3(TS / 64, 16), 256>>>(x, W_ih2, b_ih2, b_hh2);
    scan_kernel<<<8, 256>>>(W_hh2, h0_2, c0_2);
    fc_kernel<<<dim3(TS / 64, 4), 256>>>(fc_W, fc_b, out);
}

// round 14
// speedup vs baseline: 5.9527x; 1.1640x over previous
#include <cuda_runtime.h>
#include <cstdint>

#define TS 65536

// Scratch (device globals — allocation-free per harness rules)
__device__ float g_xg[(size_t)TS * 1024];   // permuted gate preactivations
__device__ float g_hs[(size_t)TS * 256];    // per-step hidden outputs

__device__ __forceinline__ uint32_t smem_u32(const void* p) {
    uint32_t r;
    asm("{ .reg .u64 t; cvta.to.shared.u64 t, %1; cvt.u32.u64 %0, t; }" : "=r"(r) : "l"(p));
    return r;
}

__device__ __forceinline__ float tanhapx(float x) {
    float y;
    asm("tanh.approx.f32 %0, %1;" : "=f"(y) : "f"(x));
    return y;
}
// accurate sigmoid for the fc epilogue (not on critical path)
__device__ __forceinline__ float fsig(float x) {
    return __fdividef(1.0f, 1.0f + __expf(-x));
}

// ---------------------------------------------------------------------------
// GEMM 1: xg[t][r] = b1[r]+b2[r] + sum_k x[t][k] * W_ih2[r][k]
// stored permuted: g_xg[t*1024 + u*4 + g], r = g*256+u  (gate order i,f,g,o)
// ---------------------------------------------------------------------------
__global__ __launch_bounds__(256) void gemm_xg_kernel(
    const float* __restrict__ X,    // [65536,256]
    const float* __restrict__ W,    // [1024,256]
    const float* __restrict__ b1,
    const float* __restrict__ b2)
{
    __shared__ float Xs[32][65];
    __shared__ float Ws[32][65];
    const int lin = threadIdx.x;
    const int tx = lin & 15, ty = lin >> 4;
    const int bt = blockIdx.x * 64;
    const int br = blockIdx.y * 64;
    float acc[4][4] = {};

    for (int k0 = 0; k0 < 256; k0 += 32) {
        int row = lin >> 3, seg = (lin & 7) << 2;
        float4 v = *(const float4*)&X[(size_t)(bt + row) * 256 + k0 + seg];
        Xs[seg+0][row] = v.x; Xs[seg+1][row] = v.y; Xs[seg+2][row] = v.z; Xs[seg+3][row] = v.w;
        float4 v2 = *(const float4*)&X[(size_t)(bt + row + 32) * 256 + k0 + seg];
        Xs[seg+0][row+32] = v2.x; Xs[seg+1][row+32] = v2.y; Xs[seg+2][row+32] = v2.z; Xs[seg+3][row+32] = v2.w;
        float4 w1 = *(const float4*)&W[(size_t)(br + row) * 256 + k0 + seg];
        Ws[seg+0][row] = w1.x; Ws[seg+1][row] = w1.y; Ws[seg+2][row] = w1.z; Ws[seg+3][row] = w1.w;
        float4 w2 = *(const float4*)&W[(size_t)(br + row + 32) * 256 + k0 + seg];
        Ws[seg+0][row+32] = w2.x; Ws[seg+1][row+32] = w2.y; Ws[seg+2][row+32] = w2.z; Ws[seg+3][row+32] = w2.w;
        __syncthreads();
#pragma unroll
        for (int kk = 0; kk < 32; kk++) {
            float a[4], bb[4];
#pragma unroll
            for (int i = 0; i < 4; i++) a[i] = Xs[kk][ty*4 + i];
#pragma unroll
            for (int j = 0; j < 4; j++) bb[j] = Ws[kk][tx*4 + j];
#pragma unroll
            for (int i = 0; i < 4; i++)
#pragma unroll
                for (int j = 0; j < 4; j++) acc[i][j] = fmaf(a[i], bb[j], acc[i][j]);
        }
        __syncthreads();
    }
#pragma unroll
    for (int j = 0; j < 4; j++) {
        int r = br + tx*4 + j;
        float bias = b1[r] + b2[r];
        int u = r & 255, g = r >> 8;
#pragma unroll
        for (int i = 0; i < 4; i++) {
            int t = bt + ty*4 + i;
            g_xg[(size_t)t * 1024 + u*4 + g] = acc[i][j] + bias;
        }
    }
}

// ---------------------------------------------------------------------------
// Sequential scan: one 8-CTA cluster. W_hh2 register-resident (128 regs/thr).
// tid = ul*8 + part ; unit u = rank*32+ul ; cols [part*32, part*32+32).
// Bank-conflict-free hv loads (rotated addresses, compile-time dests).
// W for gates i,f,o pre-scaled by 0.5 (sigmoid via 0.5+0.5*tanh, mul folded).
// xg folded into FMA accumulator init on leader lanes.
// Wait: lane 0 of each warp try_waits; other lanes reconverge via syncwarp.
// ---------------------------------------------------------------------------
__global__ void __cluster_dims__(8, 1, 1) __launch_bounds__(256, 1)
scan_kernel(const float* __restrict__ Whh,
            const float* __restrict__ h0,
            const float* __restrict__ c0)
{
    __shared__ __align__(16) float hb[2][256];
    __shared__ __align__(8)  unsigned long long mbars[2];

    const int tid  = threadIdx.x;
    const int lane = tid & 31;
    const int part = tid & 7;
    const int ul   = tid >> 3;
    uint32_t rank;
    asm("mov.u32 %0, %%cluster_ctarank;" : "=r"(rank));
    const int u    = (int)rank * 32 + ul;
    const int col0 = part * 32;

    // W rows {g*256+u}, rotated chunk order (slot 2*jj = logical chunk
    // (jj+part)&7), gates 0,1,3 pre-scaled by 0.5 for the tanh-sigmoid.
    unsigned long long w[4][16];
#pragma unroll
    for (int g = 0; g < 4; g++) {
        const float gs = (g == 2) ? 1.0f : 0.5f;
        const float* wrow = Whh + (size_t)(g * 256 + u) * 256 + col0;
#pragma unroll
        for (int jj = 0; jj < 8; jj++) {
            const int q = (jj + part) & 7;
            float4 wv = *(const float4*)(wrow + 4 * q);
            wv.x *= gs; wv.y *= gs; wv.z *= gs; wv.w *= gs;
            w[g][2*jj]     = ((unsigned long long)__float_as_uint(wv.y) << 32) | __float_as_uint(wv.x);
            w[g][2*jj + 1] = ((unsigned long long)__float_as_uint(wv.w) << 32) | __float_as_uint(wv.z);
        }
    }

    const uint32_t hb0 = smem_u32(&hb[0][0]);
    const uint32_t mb0 = smem_u32(&mbars[0]);
    const uint32_t mb_delta = mb0 - hb0;

    if (tid == 0) {
        asm volatile("mbarrier.init.shared.b64 [%0], 1;" :: "r"(mb0) : "memory");
        asm volatile("mbarrier.init.shared.b64 [%0], 1;" :: "r"(mb0 + 8) : "memory");
        // pre-arm both buffers (h_1 -> mbar[1], h_2 -> mbar[0]); 256 * 4B
        asm volatile("mbarrier.arrive.expect_tx.shared.b64 _, [%0], %1;" :: "r"(mb0), "r"(1024u) : "memory");
        asm volatile("mbarrier.arrive.expect_tx.shared.b64 _, [%0], %1;" :: "r"(mb0 + 8), "r"(1024u) : "memory");
    }
    hb[0][tid] = h0[tid];          // every CTA preloads full h0 (256 threads)
    __syncthreads();
    asm volatile("barrier.cluster.arrive.aligned;" ::: "memory");
    asm volatile("barrier.cluster.wait.aligned;"   ::: "memory");

    // leader-only state
    float c = 0.0f;
    uint32_t r_hb[8];
    float4 xg_c = make_float4(0.f,0.f,0.f,0.f), xg_n = xg_c;
    if (part == 0) {
        c = c0[u];
#pragma unroll
        for (int k = 0; k < 8; k++)
            asm("mapa.shared::cluster.u32 %0, %1, %2;" : "=r"(r_hb[k]) : "r"(hb0), "r"(k));
        xg_c = *(const float4*)(g_xg + (size_t)0 * 1024 + u * 4);
        xg_c.x *= 0.5f; xg_c.y *= 0.5f; xg_c.w *= 0.5f;
        xg_n = *(const float4*)(g_xg + (size_t)1 * 1024 + u * 4);
        xg_n.x *= 0.5f; xg_n.y *= 0.5f; xg_n.w *= 0.5f;
    }

    uint32_t par0 = 0u, par1 = 0u;

    for (int t = 0; t < TS; t++) {
        const int buf = t & 1;
        if (t > 0) {
            const uint32_t mb = mb0 + (uint32_t)buf * 8u;
            const uint32_t p  = buf ? par1 : par0;
            if (lane == 0) {
                uint32_t done;
                do {
                    asm volatile(
                        "{\n\t.reg .pred P;\n\t"
                        "mbarrier.try_wait.parity.acquire.cta.shared::cta.b64 P, [%1], %2, 0x989680;\n\t"
                        "selp.b32 %0, 1, 0, P;\n\t}"
                        : "=r"(done) : "r"(mb), "r"(p) : "memory");
                } while (!done);
            }
            __syncwarp();
            if (buf) par1 ^= 1u; else par0 ^= 1u;
            // re-arm for h_{t+2}; safe: producers of h_{t+2} need tid0's h_{t+1},
            // which tid0 sends only after this re-arm.
            if (tid == 0 && t + 2 < TS)
                asm volatile("mbarrier.arrive.expect_tx.shared.b64 _, [%0], %1;" :: "r"(mb), "r"(1024u) : "memory");
        }

        // prefetch xg for t+2 (leaders only), pre-scaled for sigmoid gates
        float4 xg2 = make_float4(0.f,0.f,0.f,0.f);
        if (part == 0 && t + 2 < TS) {
            xg2 = *(const float4*)(g_xg + (size_t)(t + 2) * 1024 + u * 4);
            xg2.x *= 0.5f; xg2.y *= 0.5f; xg2.w *= 0.5f;
        }

        // load 32 h values as 16 f32x2, chunk addresses rotated by part so the
        // 8 parts of a warp hit disjoint bank groups at each micro-step.
        unsigned long long hv[16];
        {
            const float* hwin = &hb[buf][col0];
#pragma unroll
            for (int jj = 0; jj < 8; jj++) {
                const int q = (jj + part) & 7;
                ulonglong2 v = *(const ulonglong2*)(hwin + 4 * q);
                hv[2*jj]     = v.x;
                hv[2*jj + 1] = v.y;
            }
        }

        // accumulators start at (xg, 0) on leader lanes — folds the xg add
        // into the FMA chain (off the post-reduce critical path)
        unsigned long long a0 = (part == 0) ? (unsigned long long)__float_as_uint(xg_c.x) : 0ull;
        unsigned long long a1 = (part == 0) ? (unsigned long long)__float_as_uint(xg_c.y) : 0ull;
        unsigned long long a2 = (part == 0) ? (unsigned long long)__float_as_uint(xg_c.z) : 0ull;
        unsigned long long a3 = (part == 0) ? (unsigned long long)__float_as_uint(xg_c.w) : 0ull;
#pragma unroll
        for (int j = 0; j < 16; j++) {
            asm("fma.rn.f32x2 %0, %1, %2, %0;" : "+l"(a0) : "l"(w[0][j]), "l"(hv[j]));
            asm("fma.rn.f32x2 %0, %1, %2, %0;" : "+l"(a1) : "l"(w[1][j]), "l"(hv[j]));
            asm("fma.rn.f32x2 %0, %1, %2, %0;" : "+l"(a2) : "l"(w[2][j]), "l"(hv[j]));
            asm("fma.rn.f32x2 %0, %1, %2, %0;" : "+l"(a3) : "l"(w[3][j]), "l"(hv[j]));
        }

        float s0, s1, s2, s3;
        {
            uint32_t lo, hi;
            asm("mov.b64 {%0,%1}, %2;" : "=r"(lo), "=r"(hi) : "l"(a0));
            s0 = __uint_as_float(lo) + __uint_as_float(hi);
            asm("mov.b64 {%0,%1}, %2;" : "=r"(lo), "=r"(hi) : "l"(a1));
            s1 = __uint_as_float(lo) + __uint_as_float(hi);
            asm("mov.b64 {%0,%1}, %2;" : "=r"(lo), "=r"(hi) : "l"(a2));
            s2 = __uint_as_float(lo) + __uint_as_float(hi);
            asm("mov.b64 {%0,%1}, %2;" : "=r"(lo), "=r"(hi) : "l"(a3));
            s3 = __uint_as_float(lo) + __uint_as_float(hi);
        }
#pragma unroll
        for (int m = 4; m; m >>= 1) {
            s0 += __shfl_xor_sync(0xffffffffu, s0, m);
            s1 += __shfl_xor_sync(0xffffffffu, s1, m);
            s2 += __shfl_xor_sync(0xffffffffu, s2, m);
            s3 += __shfl_xor_sync(0xffffffffu, s3, m);
        }

        if (part == 0) {
            // s0,s1,s3 are 0.5*(preact); sigmoid = 0.5 + 0.5*tanh(0.5*preact)
            float Ti = tanhapx(s0);
            float Tf = tanhapx(s1);
            float Tg = tanhapx(s2);
            float To = tanhapx(s3);
            float ii = 0.5f + 0.5f * Ti;
            float ff = 0.5f + 0.5f * Tf;
            float oo = 0.5f + 0.5f * To;
            c = ff * c + ii * Tg;
            float hnew = oo * tanhapx(c);
            if (t + 1 < TS) {
                const uint32_t hval = __float_as_uint(hnew);
                const int nbuf = buf ^ 1;
                const uint32_t doff = (uint32_t)(nbuf * 256 + u) * 4u;
                const uint32_t moff = mb_delta + (uint32_t)nbuf * 8u;
#pragma unroll
                for (int k = 0; k < 8; k++) {
                    asm volatile(
                        "st.async.weak.shared::cluster.mbarrier::complete_tx::bytes.b32 [%0], %1, [%2];"
                        :: "r"(r_hb[k] + doff), "r"(hval), "r"(r_hb[k] + moff) : "memory");
                }
            }
            g_hs[(size_t)t * 256 + u] = hnew;
            xg_c = xg_n;
            xg_n = xg2;
        }
    }
}

// ---------------------------------------------------------------------------
// GEMM 2 + epilogue: out[t][r] = 2*sigmoid( sum_k hs[t][k]*fc_W[r][k] + fc_b[r] )
// ---------------------------------------------------------------------------
__global__ __launch_bounds__(256) void fc_kernel(
    const float* __restrict__ Wf,   // [256,256]
    const float* __restrict__ bf,
    float* __restrict__ out)
{
    __shared__ float Xs[32][65];
    __shared__ float Ws[32][65];
    const int lin = threadIdx.x;
    const int tx = lin & 15, ty = lin >> 4;
    const int bt = blockIdx.x * 64;
    const int br = blockIdx.y * 64;
    float acc[4][4] = {};

    for (int k0 = 0; k0 < 256; k0 += 32) {
        int row = lin >> 3, seg = (lin & 7) << 2;
        float4 v = *(const float4*)&g_hs[(size_t)(bt + row) * 256 + k0 + seg];
        Xs[seg+0][row] = v.x; Xs[seg+1][row] = v.y; Xs[seg+2][row] = v.z; Xs[seg+3][row] = v.w;
        float4 v2 = *(const float4*)&g_hs[(size_t)(bt + row + 32) * 256 + k0 + seg];
        Xs[seg+0][row+32] = v2.x; Xs[seg+1][row+32] = v2.y; Xs[seg+2][row+32] = v2.z; Xs[seg+3][row+32] = v2.w;
        float4 w1 = *(const float4*)&Wf[(size_t)(br + row) * 256 + k0 + seg];
        Ws[seg+0][row] = w1.x; Ws[seg+1][row] = w1.y; Ws[seg+2][row] = w1.z; Ws[seg+3][row] = w1.w;
        float4 w2 = *(const float4*)&Wf[(size_t)(br + row + 32) * 256 + k0 + seg];
        Ws[seg+0][row+32] = w2.x; Ws[seg+1][row+32] = w2.y; Ws[seg+2][row+32] = w2.z; Ws[seg+3][row+32] = w2.w;
        __syncthreads();
#pragma unroll
        for (int kk = 0; kk < 32; kk++) {
            float a[4], bb[4];
#pragma unroll
            for (int i = 0; i < 4; i++) a[i] = Xs[kk][ty*4 + i];
#pragma unroll
            for (int j = 0; j < 4; j++) bb[j] = Ws[kk][tx*4 + j];
#pragma unroll
            for (int i = 0; i < 4; i++)
#pragma unroll
                for (int j = 0; j < 4; j++) acc[i][j] = fmaf(a[i], bb[j], acc[i][j]);
        }
        __syncthreads();
    }
#pragma unroll
    for (int j = 0; j < 4; j++) {
        int r = br + tx*4 + j;
        float bias = bf[r];
#pragma unroll
        for (int i = 0; i < 4; i++) {
            int t = bt + ty*4 + i;
            out[(size_t)t * 256 + r] = 2.0f * fsig(acc[i][j] + bias);
        }
    }
}

// ---------------------------------------------------------------------------
extern "C" void kernel_launch(void* const* d_in, const int* in_sizes, int n_in,
                              void* d_out, int out_size)
{
    (void)in_sizes; (void)n_in; (void)out_size;
    const float* x      = (const float*)d_in[0];
    const float* W_ih2  = (const float*)d_in[7];
    const float* W_hh2  = (const float*)d_in[8];
    const float* b_ih2  = (const float*)d_in[9];
    const float* b_hh2  = (const float*)d_in[10];
    const float* h0_2   = (const float*)d_in[11];
    const float* c0_2   = (const float*)d_in[12];
    const float* fc_W   = (const float*)d_in[13];
    const float* fc_b   = (const float*)d_in[14];
    float* out = (float*)d_out;

    gemm_xg_kernel<<<dim3(TS / 64, 16), 256>>>(x, W_ih2, b_ih2, b_hh2);
    scan_kernel<<<8, 256>>>(W_hh2, h0_2, c0_2);
    fc_kernel<<<dim3(TS / 64, 4), 256>>>(fc_W, fc_b, out);
}